// round 6
// baseline (speedup 1.0000x reference)
#include <cuda_runtime.h>
#include <cuda_bf16.h>
#include <cstdint>

#define NB   8
#define NS   2048
#define NH   256
#define NHH  128
#define NP   64
#define NQG  20
#define NTOK (NB*NS)

// ---- scratch (device globals; no allocation allowed) ----
__device__ float g_sim[NTOK];            // sim logits
__device__ float g_conf[NTOK];           // sigmoid(conf logit)
__device__ unsigned g_menc[NB*NQG];      // encoded per-group max
__device__ float g_Z[NB*NQG];
__device__ float g_cnt[NB*NQG];
__device__ float g_W[NB*NQG*NP];
__device__ float g_T[NB*NQG*NP];
__device__ float g_V[NB*NQG*NP];         // finalized smoothed vectors
__device__ unsigned g_ctr[NB];           // last-block-done counters
__device__ __nv_bfloat16 g_Bh[256*256];  // weights [n=256][k=256], bf16 hi
__device__ __nv_bfloat16 g_Bl[256*256];  // bf16 lo residual

__device__ __forceinline__ uint32_t smem_u32(const void* p) {
    uint32_t a;
    asm("{ .reg .u64 t; cvta.to.shared.u64 t, %1; cvt.u32.u64 %0, t; }" : "=r"(a) : "l"(p));
    return a;
}
#define CP_ASYNC16(smaddr, gptr) \
    asm volatile("cp.async.cg.shared.global [%0], [%1], 16;" :: "r"(smaddr), "l"(gptr))
#define CP_COMMIT() asm volatile("cp.async.commit_group;" ::: "memory")
#define CP_WAIT1()  asm volatile("cp.async.wait_group 1;" ::: "memory")
#define CP_WAIT0()  asm volatile("cp.async.wait_group 0;" ::: "memory")

__device__ __forceinline__ float dec_menc(unsigned e) {
    if (e == 0u) return -3.4e38f;
    return (e & 0x80000000u) ? __uint_as_float(e & 0x7fffffffu) : __uint_as_float(~e);
}

// ================= K_prep: transpose+split weights to bf16 hi/lo; zero accumulators =================
__global__ void k_prep(const float* __restrict__ sw1, const float* __restrict__ cw1) {
    int id = blockIdx.x * 256 + threadIdx.x;     // 32768
    int n = id >> 8, k = id & 255;               // n in [0,128), k in [0,256)
    float vs = sw1[(size_t)k * NHH + n];
    float vc = cw1[(size_t)k * NHH + n];
    __nv_bfloat16 hs = __float2bfloat16_rn(vs);
    __nv_bfloat16 ls = __float2bfloat16_rn(vs - __bfloat162float(hs));
    __nv_bfloat16 hc = __float2bfloat16_rn(vc);
    __nv_bfloat16 lc = __float2bfloat16_rn(vc - __bfloat162float(hc));
    g_Bh[n * 256 + k] = hs;
    g_Bl[n * 256 + k] = ls;
    g_Bh[(128 + n) * 256 + k] = hc;
    g_Bl[(128 + n) * 256 + k] = lc;
    if (id < NB * NQG * NP) { g_W[id] = 0.f; g_T[id] = 0.f; }
    if (id < NB * NQG) { g_menc[id] = 0u; g_Z[id] = 0.f; g_cnt[id] = 0.f; }
    if (id < NB) g_ctr[id] = 0u;
}

// ================= K_mlp: pipelined mma.sync bf16 split-GEMM + fused epilogue =================
#define MT 128
#define KC 64
#define NCHUNK (NH/KC)
#define KST 72
#define SM_AH 0
#define SM_AL (128*KST)
#define SM_B0 (2*128*KST)
#define BBUF  (2*256*KST)
#define BLOFF (256*KST)
#define MLP_SMEM ((SM_B0 + 2*BBUF) * 2)

__device__ __forceinline__ void mma_bf16(float d[4], uint32_t a0, uint32_t a1,
                                         uint32_t a2, uint32_t a3,
                                         uint32_t b0, uint32_t b1) {
    asm volatile(
        "mma.sync.aligned.m16n8k16.row.col.f32.bf16.bf16.f32 "
        "{%0,%1,%2,%3}, {%4,%5,%6,%7}, {%8,%9}, {%0,%1,%2,%3};"
        : "+f"(d[0]), "+f"(d[1]), "+f"(d[2]), "+f"(d[3])
        : "r"(a0), "r"(a1), "r"(a2), "r"(a3), "r"(b0), "r"(b1));
}

__global__ __launch_bounds__(512, 1)
void k_mlp(const float* __restrict__ x,
           const float* __restrict__ sb1, const float* __restrict__ sb2,
           const float* __restrict__ cb1, const float* __restrict__ cb2,
           const float* __restrict__ sw2, const float* __restrict__ cw2,
           const int* __restrict__ qs)
{
    extern __shared__ __nv_bfloat16 sm[];
    __shared__ float b1s[256], w2s[256];
    __shared__ float part[128][4];

    const int tid  = threadIdx.x;
    const int wid  = tid >> 5;
    const int lane = tid & 31;
    const int gid  = lane >> 2;
    const int tig  = lane & 3;
    const int mw   = wid & 3;
    const int nw   = wid >> 2;
    const int m0w  = mw * 32;
    const int n0w  = nw * 64;
    const int row0 = blockIdx.x * MT;
    const uint32_t smb = smem_u32(sm);

    if (tid < 256) {
        b1s[tid] = (tid < 128) ? sb1[tid] : cb1[tid - 128];
        w2s[tid] = (tid < 128) ? sw2[tid] : cw2[tid - 128];
    }

    float d[2][8][4];
    #pragma unroll
    for (int mi = 0; mi < 2; ++mi)
        #pragma unroll
        for (int ni = 0; ni < 8; ++ni)
            #pragma unroll
            for (int j = 0; j < 4; ++j) d[mi][ni][j] = 0.f;

    // ---- issue B chunk 0 (cp.async) ----
    #pragma unroll
    for (int i = 0; i < 4; ++i) {
        int idx = tid * 4 + i;
        int n = idx >> 3, k = (idx & 7) * 8;
        uint32_t dh = smb + 2 * (SM_B0 + n * KST + k);
        CP_ASYNC16(dh, &g_Bh[n * 256 + k]);
        CP_ASYNC16(dh + 2 * BLOFF, &g_Bl[n * 256 + k]);
    }
    CP_COMMIT();

    // ---- load A chunk 0 into regs ----
    float4 av[4];
    #pragma unroll
    for (int i = 0; i < 4; ++i) {
        int idx = tid * 4 + i;
        int row = idx >> 4, k = (idx & 15) * 4;
        av[i] = *(const float4*)&x[(size_t)(row0 + row) * NH + k];
    }

    for (int c = 0; c < NCHUNK; ++c) {
        const int buf = c & 1;
        if (c < NCHUNK - 1) {
            const int kb = (c + 1) * KC;
            #pragma unroll
            for (int i = 0; i < 4; ++i) {
                int idx = tid * 4 + i;
                int n = idx >> 3, k = (idx & 7) * 8;
                uint32_t dh = smb + 2 * (SM_B0 + (buf ^ 1) * BBUF + n * KST + k);
                CP_ASYNC16(dh, &g_Bh[n * 256 + kb + k]);
                CP_ASYNC16(dh + 2 * BLOFF, &g_Bl[n * 256 + kb + k]);
            }
            CP_COMMIT();
        }
        #pragma unroll
        for (int i = 0; i < 4; ++i) {
            int idx = tid * 4 + i;
            int row = idx >> 4, k = (idx & 15) * 4;
            float4 v = av[i];
            __nv_bfloat16 h0 = __float2bfloat16_rn(v.x), h1 = __float2bfloat16_rn(v.y);
            __nv_bfloat16 h2 = __float2bfloat16_rn(v.z), h3 = __float2bfloat16_rn(v.w);
            __nv_bfloat162 hA = {h0, h1}, hB = {h2, h3};
            __nv_bfloat162 lA = {__float2bfloat16_rn(v.x - __bfloat162float(h0)),
                                 __float2bfloat16_rn(v.y - __bfloat162float(h1))};
            __nv_bfloat162 lB = {__float2bfloat16_rn(v.z - __bfloat162float(h2)),
                                 __float2bfloat16_rn(v.w - __bfloat162float(h3))};
            uint2 hw = {*(uint32_t*)&hA, *(uint32_t*)&hB};
            uint2 lw = {*(uint32_t*)&lA, *(uint32_t*)&lB};
            *(uint2*)&sm[SM_AH + row * KST + k] = hw;
            *(uint2*)&sm[SM_AL + row * KST + k] = lw;
        }
        if (c < NCHUNK - 1) {
            const int kb = (c + 1) * KC;
            #pragma unroll
            for (int i = 0; i < 4; ++i) {
                int idx = tid * 4 + i;
                int row = idx >> 4, k = (idx & 15) * 4;
                av[i] = *(const float4*)&x[(size_t)(row0 + row) * NH + kb + k];
            }
        }
        if (c < NCHUNK - 1) { CP_WAIT1(); } else { CP_WAIT0(); }
        __syncthreads();

        const int B0 = SM_B0 + buf * BBUF;
        #pragma unroll
        for (int ks = 0; ks < KC / 16; ++ks) {
            const int kk = ks * 16;
            uint32_t ah[2][4], al[2][4];
            #pragma unroll
            for (int mi = 0; mi < 2; ++mi) {
                int off = (m0w + mi * 16 + gid) * KST + kk + 2 * tig;
                ah[mi][0] = *(const uint32_t*)&sm[SM_AH + off];
                ah[mi][1] = *(const uint32_t*)&sm[SM_AH + off + 8 * KST];
                ah[mi][2] = *(const uint32_t*)&sm[SM_AH + off + 8];
                ah[mi][3] = *(const uint32_t*)&sm[SM_AH + off + 8 * KST + 8];
                al[mi][0] = *(const uint32_t*)&sm[SM_AL + off];
                al[mi][1] = *(const uint32_t*)&sm[SM_AL + off + 8 * KST];
                al[mi][2] = *(const uint32_t*)&sm[SM_AL + off + 8];
                al[mi][3] = *(const uint32_t*)&sm[SM_AL + off + 8 * KST + 8];
            }
            #pragma unroll
            for (int ni = 0; ni < 8; ++ni) {
                int offb = B0 + (n0w + ni * 8 + gid) * KST + kk + 2 * tig;
                uint32_t b0 = *(const uint32_t*)&sm[offb];
                uint32_t b1 = *(const uint32_t*)&sm[offb + 8];
                #pragma unroll
                for (int mi = 0; mi < 2; ++mi) {
                    mma_bf16(d[mi][ni], ah[mi][0], ah[mi][1], ah[mi][2], ah[mi][3], b0, b1);
                    mma_bf16(d[mi][ni], al[mi][0], al[mi][1], al[mi][2], al[mi][3], b0, b1);
                }
            }
            #pragma unroll
            for (int ni = 0; ni < 8; ++ni) {
                int offb = B0 + BLOFF + (n0w + ni * 8 + gid) * KST + kk + 2 * tig;
                uint32_t b0 = *(const uint32_t*)&sm[offb];
                uint32_t b1 = *(const uint32_t*)&sm[offb + 8];
                #pragma unroll
                for (int mi = 0; mi < 2; ++mi)
                    mma_bf16(d[mi][ni], ah[mi][0], ah[mi][1], ah[mi][2], ah[mi][3], b0, b1);
            }
        }
        __syncthreads();
    }

    // ---- epilogue ----
    float p[2][2];
    #pragma unroll
    for (int mi = 0; mi < 2; ++mi) {
        p[mi][0] = 0.f; p[mi][1] = 0.f;
        #pragma unroll
        for (int ni = 0; ni < 8; ++ni) {
            int cb = n0w + ni * 8 + 2 * tig;
            #pragma unroll
            for (int j = 0; j < 2; ++j) {
                float h0 = fmaxf(d[mi][ni][j]     + b1s[cb + j], 0.f);
                float h1 = fmaxf(d[mi][ni][2 + j] + b1s[cb + j], 0.f);
                p[mi][0] = fmaf(h0, w2s[cb + j], p[mi][0]);
                p[mi][1] = fmaf(h1, w2s[cb + j], p[mi][1]);
            }
        }
    }
    #pragma unroll
    for (int off = 1; off <= 2; off <<= 1) {
        #pragma unroll
        for (int mi = 0; mi < 2; ++mi) {
            p[mi][0] += __shfl_xor_sync(0xffffffffu, p[mi][0], off);
            p[mi][1] += __shfl_xor_sync(0xffffffffu, p[mi][1], off);
        }
    }
    if (tig == 0) {
        #pragma unroll
        for (int mi = 0; mi < 2; ++mi) {
            part[m0w + mi * 16 + gid][nw]     = p[mi][0];
            part[m0w + mi * 16 + gid + 8][nw] = p[mi][1];
        }
    }
    __syncthreads();
    if (tid < 128) {
        int row = row0 + tid;
        float sv = part[tid][0] + part[tid][1] + sb2[0];
        float cl = part[tid][2] + part[tid][3] + cb2[0];
        g_sim[row]  = sv;
        g_conf[row] = 1.f / (1.f + __expf(-cl));
        unsigned bits = __float_as_uint(sv);
        unsigned enc = (bits & 0x80000000u) ? ~bits : (bits | 0x80000000u);
        int b = row >> 11;
        atomicMax(&g_menc[b * NQG + qs[row]], enc);
    }
}

// ================= K_accum: exp/Z/count + group sums + last-block V finalize =================
__global__ __launch_bounds__(256) void k_accum(const float* __restrict__ px,
                                               const int* __restrict__ qs) {
    const int b = blockIdx.x >> 5;
    const int chunk = blockIdx.x & 31;
    const int t0 = b * NS + chunk * 64;
    const int p = threadIdx.x & 63;
    const int u = threadIdx.x >> 6;
    const int bg = b * NQG;
    __shared__ float accW[4][NQG][NP];
    __shared__ float accT[4][NQG][NP];
    __shared__ float esh[64];
    __shared__ int   qsh[64];
    __shared__ float Msh[NQG], Zsh[NQG];
    __shared__ int   csh[NQG];
    __shared__ int   isLast;
    if (threadIdx.x < NQG) {
        Msh[threadIdx.x] = fmaxf(dec_menc(g_menc[bg + threadIdx.x]), 0.f);
        Zsh[threadIdx.x] = 0.f; csh[threadIdx.x] = 0;
    }
    #pragma unroll
    for (int g = 0; g < NQG; ++g) { accW[u][g][p] = 0.f; accT[u][g][p] = 0.f; }
    __syncthreads();
    if (threadIdx.x < 64) {
        int q = qs[t0 + threadIdx.x];
        qsh[threadIdx.x] = q;
        float e = __expf(g_sim[t0 + threadIdx.x] - Msh[q]);
        esh[threadIdx.x] = e;
        atomicAdd(&Zsh[q], e);
        atomicAdd(&csh[q], 1);
    }
    __syncthreads();
    const int tb = u * 16;
    float pxv[16];
    const float* base = px + (size_t)(t0 + tb) * NP + p;
    #pragma unroll
    for (int k = 0; k < 16; ++k) pxv[k] = base[(size_t)k * NP];
    #pragma unroll
    for (int k = 0; k < 16; ++k) {
        int g = qsh[tb + k];
        accW[u][g][p] = fmaf(esh[tb + k], pxv[k], accW[u][g][p]);
        accT[u][g][p] += pxv[k];
    }
    __syncthreads();
    for (int i = threadIdx.x; i < NQG * NP; i += 256) {
        int g = i >> 6, pp = i & 63;
        float w = accW[0][g][pp] + accW[1][g][pp] + accW[2][g][pp] + accW[3][g][pp];
        float t = accT[0][g][pp] + accT[1][g][pp] + accT[2][g][pp] + accT[3][g][pp];
        atomicAdd(&g_W[(bg + g) * NP + pp], w);
        atomicAdd(&g_T[(bg + g) * NP + pp], t);
    }
    if (threadIdx.x < NQG) {
        atomicAdd(&g_Z[bg + threadIdx.x], Zsh[threadIdx.x]);
        atomicAdd(&g_cnt[bg + threadIdx.x], (float)csh[threadIdx.x]);
    }
    // ---- last block of this batch finalizes V ----
    __threadfence();
    __syncthreads();
    if (threadIdx.x == 0) isLast = (atomicAdd(&g_ctr[b], 1u) == 31u);
    __syncthreads();
    if (!isLast) return;
    __threadfence();
    // reuse smem: tall per p in esh[64]; per-group em/Zfull in Zsh
    __shared__ float Tl[NQG][NP];
    for (int i = threadIdx.x; i < NQG * NP; i += 256) {
        int g = i >> 6, pp = i & 63;
        Tl[g][pp] = __ldcg(&g_T[(bg + g) * NP + pp]);
    }
    if (threadIdx.x < NQG) {
        float em = __expf(-Msh[threadIdx.x]);
        float Z  = __ldcg(&g_Z[bg + threadIdx.x]) +
                   ((float)NS - __ldcg(&g_cnt[bg + threadIdx.x])) * em;
        Zsh[threadIdx.x] = em / Z;         // scale for out-group term
        csh[threadIdx.x] = __float_as_int(1.f / Z);  // stash 1/Z
    }
    __syncthreads();
    if (threadIdx.x < NP) {
        float t = 0.f;
        #pragma unroll
        for (int g = 0; g < NQG; ++g) t += Tl[g][threadIdx.x];
        esh[threadIdx.x] = t;
    }
    __syncthreads();
    for (int i = threadIdx.x; i < NQG * NP; i += 256) {
        int g = i >> 6, pp = i & 63;
        float invZ = __int_as_float(csh[g]);
        float w = __ldcg(&g_W[(bg + g) * NP + pp]);
        g_V[(bg + g) * NP + pp] = w * invZ + Zsh[g] * (esh[pp] - Tl[g][pp]);
    }
}

// ================= K_out: pure streaming blend =================
__global__ __launch_bounds__(256) void k_out(const float* __restrict__ px,
                                             const int* __restrict__ qs,
                                             float* __restrict__ out) {
    int fid = blockIdx.x * 256 + threadIdx.x;   // 262144 float4
    int t  = fid >> 4;
    int pq = fid & 15;
    int b  = t >> 11;
    int q  = __ldg(&qs[t]);
    float c = g_conf[t];
    float4 pv = *(const float4*)&px[(size_t)t * NP + pq * 4];
    float4 vv = *(const float4*)&g_V[((b * NQG) + q) * NP + pq * 4];
    float ic = 1.f - c;
    float4 o;
    o.x = fmaf(c, pv.x, ic * vv.x);
    o.y = fmaf(c, pv.y, ic * vv.y);
    o.z = fmaf(c, pv.z, ic * vv.z);
    o.w = fmaf(c, pv.w, ic * vv.w);
    *(float4*)&out[(size_t)t * NP + pq * 4] = o;
}

extern "C" void kernel_launch(void* const* d_in, const int* in_sizes, int n_in,
                              void* d_out, int out_size) {
    const float* x   = (const float*)d_in[0];
    const float* px  = (const float*)d_in[1];
    const float* sw1 = (const float*)d_in[2];
    const float* sb1 = (const float*)d_in[3];
    const float* sw2 = (const float*)d_in[4];
    const float* sb2 = (const float*)d_in[5];
    const float* cw1 = (const float*)d_in[6];
    const float* cb1 = (const float*)d_in[7];
    const float* cw2 = (const float*)d_in[8];
    const float* cb2 = (const float*)d_in[9];
    const int*   qs  = (const int*)d_in[10];
    float* out = (float*)d_out;

    cudaFuncSetAttribute(k_mlp, cudaFuncAttributeMaxDynamicSharedMemorySize, MLP_SMEM);

    k_prep<<<128, 256>>>(sw1, cw1);
    k_mlp<<<NTOK / MT, 512, MLP_SMEM>>>(x, sb1, sb2, cb1, cb2, sw2, cw2, qs);
    k_accum<<<NB * 32, 256>>>(px, qs);
    k_out<<<NTOK * 16 / 256, 256>>>(px, qs, out);
}

// round 7
// speedup vs baseline: 1.0014x; 1.0014x over previous
#include <cuda_runtime.h>
#include <cuda_bf16.h>
#include <cstdint>

#define NB   8
#define NS   2048
#define NH   256
#define NHH  128
#define NP   64
#define NQG  20
#define NTOK (NB*NS)

// ---- scratch (device globals; no allocation allowed) ----
__device__ float g_sim[NTOK];            // sim logits
__device__ float g_conf[NTOK];           // sigmoid(conf logit)
__device__ unsigned g_menc[NB*NQG];      // encoded per-group max
__device__ float g_Z[NB*NQG];
__device__ float g_cnt[NB*NQG];
__device__ float g_W[NB*NQG*NP];
__device__ float g_T[NB*NQG*NP];
__device__ float g_V[NB*NQG*NP];         // finalized smoothed vectors
__device__ __nv_bfloat16 g_Bh[256*256];  // weights [n=256][k=256], bf16 hi
__device__ __nv_bfloat16 g_Bl[256*256];  // bf16 lo residual

__device__ __forceinline__ uint32_t smem_u32(const void* p) {
    uint32_t a;
    asm("{ .reg .u64 t; cvta.to.shared.u64 t, %1; cvt.u32.u64 %0, t; }" : "=r"(a) : "l"(p));
    return a;
}
#define CP_ASYNC16(smaddr, gptr) \
    asm volatile("cp.async.cg.shared.global [%0], [%1], 16;" :: "r"(smaddr), "l"(gptr))
#define CP_COMMIT() asm volatile("cp.async.commit_group;" ::: "memory")
#define CP_WAIT1()  asm volatile("cp.async.wait_group 1;" ::: "memory")
#define CP_WAIT0()  asm volatile("cp.async.wait_group 0;" ::: "memory")

__device__ __forceinline__ float dec_menc(unsigned e) {
    if (e == 0u) return -3.4e38f;
    return (e & 0x80000000u) ? __uint_as_float(e & 0x7fffffffu) : __uint_as_float(~e);
}

// ================= K_prep: transpose+split weights to bf16 hi/lo; zero accumulators =================
__global__ void k_prep(const float* __restrict__ sw1, const float* __restrict__ cw1) {
    int id = blockIdx.x * 256 + threadIdx.x;     // 32768
    int n = id >> 8, k = id & 255;               // n in [0,128), k in [0,256)
    float vs = sw1[(size_t)k * NHH + n];
    float vc = cw1[(size_t)k * NHH + n];
    __nv_bfloat16 hs = __float2bfloat16_rn(vs);
    __nv_bfloat16 ls = __float2bfloat16_rn(vs - __bfloat162float(hs));
    __nv_bfloat16 hc = __float2bfloat16_rn(vc);
    __nv_bfloat16 lc = __float2bfloat16_rn(vc - __bfloat162float(hc));
    g_Bh[n * 256 + k] = hs;
    g_Bl[n * 256 + k] = ls;
    g_Bh[(128 + n) * 256 + k] = hc;
    g_Bl[(128 + n) * 256 + k] = lc;
    if (id < NB * NQG * NP) { g_W[id] = 0.f; g_T[id] = 0.f; }
    if (id < NB * NQG) { g_menc[id] = 0u; g_Z[id] = 0.f; g_cnt[id] = 0.f; }
}

// ================= K_mlp: pipelined mma.sync bf16 split-GEMM + fused epilogue =================
#define MT 128
#define KC 64
#define NCHUNK (NH/KC)
#define KST 72
#define SM_AH 0
#define SM_AL (128*KST)
#define SM_B0 (2*128*KST)
#define BBUF  (2*256*KST)
#define BLOFF (256*KST)
#define MLP_SMEM ((SM_B0 + 2*BBUF) * 2)

__device__ __forceinline__ void mma_bf16(float d[4], uint32_t a0, uint32_t a1,
                                         uint32_t a2, uint32_t a3,
                                         uint32_t b0, uint32_t b1) {
    asm volatile(
        "mma.sync.aligned.m16n8k16.row.col.f32.bf16.bf16.f32 "
        "{%0,%1,%2,%3}, {%4,%5,%6,%7}, {%8,%9}, {%0,%1,%2,%3};"
        : "+f"(d[0]), "+f"(d[1]), "+f"(d[2]), "+f"(d[3])
        : "r"(a0), "r"(a1), "r"(a2), "r"(a3), "r"(b0), "r"(b1));
}

__global__ __launch_bounds__(512, 1)
void k_mlp(const float* __restrict__ x,
           const float* __restrict__ sb1, const float* __restrict__ sb2,
           const float* __restrict__ cb1, const float* __restrict__ cb2,
           const float* __restrict__ sw2, const float* __restrict__ cw2,
           const int* __restrict__ qs)
{
    extern __shared__ __nv_bfloat16 sm[];
    __shared__ float b1s[256], w2s[256];
    __shared__ float part[128][4];

    const int tid  = threadIdx.x;
    const int wid  = tid >> 5;
    const int lane = tid & 31;
    const int gid  = lane >> 2;
    const int tig  = lane & 3;
    const int mw   = wid & 3;
    const int nw   = wid >> 2;
    const int m0w  = mw * 32;
    const int n0w  = nw * 64;
    const int row0 = blockIdx.x * MT;
    const uint32_t smb = smem_u32(sm);

    if (tid < 256) {
        b1s[tid] = (tid < 128) ? sb1[tid] : cb1[tid - 128];
        w2s[tid] = (tid < 128) ? sw2[tid] : cw2[tid - 128];
    }

    float d[2][8][4];
    #pragma unroll
    for (int mi = 0; mi < 2; ++mi)
        #pragma unroll
        for (int ni = 0; ni < 8; ++ni)
            #pragma unroll
            for (int j = 0; j < 4; ++j) d[mi][ni][j] = 0.f;

    // ---- issue B chunk 0 (cp.async) ----
    #pragma unroll
    for (int i = 0; i < 4; ++i) {
        int idx = tid * 4 + i;
        int n = idx >> 3, k = (idx & 7) * 8;
        uint32_t dh = smb + 2 * (SM_B0 + n * KST + k);
        CP_ASYNC16(dh, &g_Bh[n * 256 + k]);
        CP_ASYNC16(dh + 2 * BLOFF, &g_Bl[n * 256 + k]);
    }
    CP_COMMIT();

    // ---- load A chunk 0 into regs ----
    float4 av[4];
    #pragma unroll
    for (int i = 0; i < 4; ++i) {
        int idx = tid * 4 + i;
        int row = idx >> 4, k = (idx & 15) * 4;
        av[i] = *(const float4*)&x[(size_t)(row0 + row) * NH + k];
    }

    for (int c = 0; c < NCHUNK; ++c) {
        const int buf = c & 1;
        if (c < NCHUNK - 1) {
            const int kb = (c + 1) * KC;
            #pragma unroll
            for (int i = 0; i < 4; ++i) {
                int idx = tid * 4 + i;
                int n = idx >> 3, k = (idx & 7) * 8;
                uint32_t dh = smb + 2 * (SM_B0 + (buf ^ 1) * BBUF + n * KST + k);
                CP_ASYNC16(dh, &g_Bh[n * 256 + kb + k]);
                CP_ASYNC16(dh + 2 * BLOFF, &g_Bl[n * 256 + kb + k]);
            }
            CP_COMMIT();
        }
        #pragma unroll
        for (int i = 0; i < 4; ++i) {
            int idx = tid * 4 + i;
            int row = idx >> 4, k = (idx & 15) * 4;
            float4 v = av[i];
            __nv_bfloat16 h0 = __float2bfloat16_rn(v.x), h1 = __float2bfloat16_rn(v.y);
            __nv_bfloat16 h2 = __float2bfloat16_rn(v.z), h3 = __float2bfloat16_rn(v.w);
            __nv_bfloat162 hA = {h0, h1}, hB = {h2, h3};
            __nv_bfloat162 lA = {__float2bfloat16_rn(v.x - __bfloat162float(h0)),
                                 __float2bfloat16_rn(v.y - __bfloat162float(h1))};
            __nv_bfloat162 lB = {__float2bfloat16_rn(v.z - __bfloat162float(h2)),
                                 __float2bfloat16_rn(v.w - __bfloat162float(h3))};
            uint2 hw = {*(uint32_t*)&hA, *(uint32_t*)&hB};
            uint2 lw = {*(uint32_t*)&lA, *(uint32_t*)&lB};
            *(uint2*)&sm[SM_AH + row * KST + k] = hw;
            *(uint2*)&sm[SM_AL + row * KST + k] = lw;
        }
        if (c < NCHUNK - 1) {
            const int kb = (c + 1) * KC;
            #pragma unroll
            for (int i = 0; i < 4; ++i) {
                int idx = tid * 4 + i;
                int row = idx >> 4, k = (idx & 15) * 4;
                av[i] = *(const float4*)&x[(size_t)(row0 + row) * NH + kb + k];
            }
        }
        if (c < NCHUNK - 1) { CP_WAIT1(); } else { CP_WAIT0(); }
        __syncthreads();

        const int B0 = SM_B0 + buf * BBUF;
        #pragma unroll
        for (int ks = 0; ks < KC / 16; ++ks) {
            const int kk = ks * 16;
            uint32_t ah[2][4], al[2][4];
            #pragma unroll
            for (int mi = 0; mi < 2; ++mi) {
                int off = (m0w + mi * 16 + gid) * KST + kk + 2 * tig;
                ah[mi][0] = *(const uint32_t*)&sm[SM_AH + off];
                ah[mi][1] = *(const uint32_t*)&sm[SM_AH + off + 8 * KST];
                ah[mi][2] = *(const uint32_t*)&sm[SM_AH + off + 8];
                ah[mi][3] = *(const uint32_t*)&sm[SM_AH + off + 8 * KST + 8];
                al[mi][0] = *(const uint32_t*)&sm[SM_AL + off];
                al[mi][1] = *(const uint32_t*)&sm[SM_AL + off + 8 * KST];
                al[mi][2] = *(const uint32_t*)&sm[SM_AL + off + 8];
                al[mi][3] = *(const uint32_t*)&sm[SM_AL + off + 8 * KST + 8];
            }
            #pragma unroll
            for (int ni = 0; ni < 8; ++ni) {
                int offb = B0 + (n0w + ni * 8 + gid) * KST + kk + 2 * tig;
                uint32_t b0 = *(const uint32_t*)&sm[offb];
                uint32_t b1 = *(const uint32_t*)&sm[offb + 8];
                #pragma unroll
                for (int mi = 0; mi < 2; ++mi) {
                    mma_bf16(d[mi][ni], ah[mi][0], ah[mi][1], ah[mi][2], ah[mi][3], b0, b1);
                    mma_bf16(d[mi][ni], al[mi][0], al[mi][1], al[mi][2], al[mi][3], b0, b1);
                }
            }
            #pragma unroll
            for (int ni = 0; ni < 8; ++ni) {
                int offb = B0 + BLOFF + (n0w + ni * 8 + gid) * KST + kk + 2 * tig;
                uint32_t b0 = *(const uint32_t*)&sm[offb];
                uint32_t b1 = *(const uint32_t*)&sm[offb + 8];
                #pragma unroll
                for (int mi = 0; mi < 2; ++mi)
                    mma_bf16(d[mi][ni], ah[mi][0], ah[mi][1], ah[mi][2], ah[mi][3], b0, b1);
            }
        }
        __syncthreads();
    }

    // ---- epilogue ----
    float p[2][2];
    #pragma unroll
    for (int mi = 0; mi < 2; ++mi) {
        p[mi][0] = 0.f; p[mi][1] = 0.f;
        #pragma unroll
        for (int ni = 0; ni < 8; ++ni) {
            int cb = n0w + ni * 8 + 2 * tig;
            #pragma unroll
            for (int j = 0; j < 2; ++j) {
                float h0 = fmaxf(d[mi][ni][j]     + b1s[cb + j], 0.f);
                float h1 = fmaxf(d[mi][ni][2 + j] + b1s[cb + j], 0.f);
                p[mi][0] = fmaf(h0, w2s[cb + j], p[mi][0]);
                p[mi][1] = fmaf(h1, w2s[cb + j], p[mi][1]);
            }
        }
    }
    #pragma unroll
    for (int off = 1; off <= 2; off <<= 1) {
        #pragma unroll
        for (int mi = 0; mi < 2; ++mi) {
            p[mi][0] += __shfl_xor_sync(0xffffffffu, p[mi][0], off);
            p[mi][1] += __shfl_xor_sync(0xffffffffu, p[mi][1], off);
        }
    }
    if (tig == 0) {
        #pragma unroll
        for (int mi = 0; mi < 2; ++mi) {
            part[m0w + mi * 16 + gid][nw]     = p[mi][0];
            part[m0w + mi * 16 + gid + 8][nw] = p[mi][1];
        }
    }
    __syncthreads();
    if (tid < 128) {
        int row = row0 + tid;
        float sv = part[tid][0] + part[tid][1] + sb2[0];
        float cl = part[tid][2] + part[tid][3] + cb2[0];
        g_sim[row]  = sv;
        g_conf[row] = 1.f / (1.f + __expf(-cl));
        unsigned bits = __float_as_uint(sv);
        unsigned enc = (bits & 0x80000000u) ? ~bits : (bits | 0x80000000u);
        int b = row >> 11;
        atomicMax(&g_menc[b * NQG + qs[row]], enc);
    }
}

// ================= K_accum: exp/Z/count + per-group weighted sums =================
__global__ __launch_bounds__(256) void k_accum(const float* __restrict__ px,
                                               const int* __restrict__ qs) {
    const int b = blockIdx.x >> 5;
    const int chunk = blockIdx.x & 31;
    const int t0 = b * NS + chunk * 64;
    const int p = threadIdx.x & 63;
    const int u = threadIdx.x >> 6;
    const int bg = b * NQG;
    __shared__ float accW[4][NQG][NP];
    __shared__ float accT[4][NQG][NP];
    __shared__ float esh[64];
    __shared__ int   qsh[64];
    __shared__ float Msh[NQG], Zsh[NQG];
    __shared__ int   csh[NQG];
    if (threadIdx.x < NQG) {
        Msh[threadIdx.x] = fmaxf(dec_menc(g_menc[bg + threadIdx.x]), 0.f);
        Zsh[threadIdx.x] = 0.f; csh[threadIdx.x] = 0;
    }
    #pragma unroll
    for (int g = 0; g < NQG; ++g) { accW[u][g][p] = 0.f; accT[u][g][p] = 0.f; }
    __syncthreads();
    if (threadIdx.x < 64) {
        int q = qs[t0 + threadIdx.x];
        qsh[threadIdx.x] = q;
        float e = __expf(g_sim[t0 + threadIdx.x] - Msh[q]);
        esh[threadIdx.x] = e;
        atomicAdd(&Zsh[q], e);
        atomicAdd(&csh[q], 1);
    }
    __syncthreads();
    const int tb = u * 16;
    float pxv[16];
    const float* base = px + (size_t)(t0 + tb) * NP + p;
    #pragma unroll
    for (int k = 0; k < 16; ++k) pxv[k] = base[(size_t)k * NP];
    #pragma unroll
    for (int k = 0; k < 16; ++k) {
        int g = qsh[tb + k];
        accW[u][g][p] = fmaf(esh[tb + k], pxv[k], accW[u][g][p]);
        accT[u][g][p] += pxv[k];
    }
    __syncthreads();
    for (int i = threadIdx.x; i < NQG * NP; i += 256) {
        int g = i >> 6, pp = i & 63;
        float w = accW[0][g][pp] + accW[1][g][pp] + accW[2][g][pp] + accW[3][g][pp];
        float t = accT[0][g][pp] + accT[1][g][pp] + accT[2][g][pp] + accT[3][g][pp];
        atomicAdd(&g_W[(bg + g) * NP + pp], w);
        atomicAdd(&g_T[(bg + g) * NP + pp], t);
    }
    if (threadIdx.x < NQG) {
        atomicAdd(&g_Z[bg + threadIdx.x], Zsh[threadIdx.x]);
        atomicAdd(&g_cnt[bg + threadIdx.x], (float)csh[threadIdx.x]);
    }
}

// ================= K_fin: finalize V (one block per batch) =================
__global__ __launch_bounds__(256) void k_fin() {
    const int b = blockIdx.x;
    const int bg = b * NQG;
    const int tid = threadIdx.x;
    __shared__ float Tl[NQG][NP];
    __shared__ float tall[NP];
    __shared__ float sc_out[NQG];   // em/Z
    __shared__ float sc_inv[NQG];   // 1/Z
    for (int i = tid; i < NQG * NP; i += 256) {
        int g = i >> 6, p = i & 63;
        Tl[g][p] = g_T[(bg + g) * NP + p];
    }
    if (tid < NQG) {
        float M  = fmaxf(dec_menc(g_menc[bg + tid]), 0.f);
        float em = __expf(-M);
        float Z  = g_Z[bg + tid] + ((float)NS - g_cnt[bg + tid]) * em;
        sc_out[tid] = em / Z;
        sc_inv[tid] = 1.f / Z;
    }
    __syncthreads();
    if (tid < NP) {
        float t = 0.f;
        #pragma unroll
        for (int g = 0; g < NQG; ++g) t += Tl[g][tid];
        tall[tid] = t;
    }
    __syncthreads();
    for (int i = tid; i < NQG * NP; i += 256) {
        int g = i >> 6, p = i & 63;
        g_V[(bg + g) * NP + p] = g_W[(bg + g) * NP + p] * sc_inv[g] +
                                 sc_out[g] * (tall[p] - Tl[g][p]);
    }
}

// ================= K_out: pure streaming blend =================
__global__ __launch_bounds__(256) void k_out(const float* __restrict__ px,
                                             const int* __restrict__ qs,
                                             float* __restrict__ out) {
    int fid = blockIdx.x * 256 + threadIdx.x;   // 262144 float4
    int t  = fid >> 4;
    int pq = fid & 15;
    int b  = t >> 11;
    int q  = __ldg(&qs[t]);
    float c = g_conf[t];
    float4 pv = *(const float4*)&px[(size_t)t * NP + pq * 4];
    float4 vv = *(const float4*)&g_V[((b * NQG) + q) * NP + pq * 4];
    float ic = 1.f - c;
    float4 o;
    o.x = fmaf(c, pv.x, ic * vv.x);
    o.y = fmaf(c, pv.y, ic * vv.y);
    o.z = fmaf(c, pv.z, ic * vv.z);
    o.w = fmaf(c, pv.w, ic * vv.w);
    *(float4*)&out[(size_t)t * NP + pq * 4] = o;
}

extern "C" void kernel_launch(void* const* d_in, const int* in_sizes, int n_in,
                              void* d_out, int out_size) {
    const float* x   = (const float*)d_in[0];
    const float* px  = (const float*)d_in[1];
    const float* sw1 = (const float*)d_in[2];
    const float* sb1 = (const float*)d_in[3];
    const float* sw2 = (const float*)d_in[4];
    const float* sb2 = (const float*)d_in[5];
    const float* cw1 = (const float*)d_in[6];
    const float* cb1 = (const float*)d_in[7];
    const float* cw2 = (const float*)d_in[8];
    const float* cb2 = (const float*)d_in[9];
    const int*   qs  = (const int*)d_in[10];
    float* out = (float*)d_out;

    cudaFuncSetAttribute(k_mlp, cudaFuncAttributeMaxDynamicSharedMemorySize, MLP_SMEM);

    k_prep<<<128, 256>>>(sw1, cw1);
    k_mlp<<<NTOK / MT, 512, MLP_SMEM>>>(x, sb1, sb2, cb1, cb2, sw2, cw2, qs);
    k_accum<<<NB * 32, 256>>>(px, qs);
    k_fin<<<NB, 256>>>();
    k_out<<<NTOK * 16 / 256, 256>>>(px, qs, out);
}

// round 8
// speedup vs baseline: 1.0624x; 1.0609x over previous
#include <cuda_runtime.h>
#include <cuda_bf16.h>
#include <cstdint>

#define NB   8
#define NS   2048
#define NH   256
#define NHH  128
#define NP   64
#define NQG  20
#define NTOK (NB*NS)

// ---- scratch (device globals; no allocation allowed) ----
__device__ float g_e[NTOK];              // exp(sim logit), clamped
__device__ float g_conf[NTOK];           // sigmoid(conf logit)
__device__ float g_Z[NB*NQG];            // in-group sum of exp
__device__ float g_cnt[NB*NQG];          // group counts
__device__ float g_W[NB*NQG*NP];         // exp-weighted param sums
__device__ float g_T[NB*NQG*NP];         // plain param sums
__device__ __nv_bfloat16 g_Bh[256*256];  // weights [n=256][k=256], bf16 hi
__device__ __nv_bfloat16 g_Bl[256*256];  // bf16 lo residual

__device__ __forceinline__ uint32_t smem_u32(const void* p) {
    uint32_t a;
    asm("{ .reg .u64 t; cvta.to.shared.u64 t, %1; cvt.u32.u64 %0, t; }" : "=r"(a) : "l"(p));
    return a;
}
#define CP_ASYNC16(smaddr, gptr) \
    asm volatile("cp.async.cg.shared.global [%0], [%1], 16;" :: "r"(smaddr), "l"(gptr))
#define CP_COMMIT() asm volatile("cp.async.commit_group;" ::: "memory")
#define CP_WAIT1()  asm volatile("cp.async.wait_group 1;" ::: "memory")
#define CP_WAIT0()  asm volatile("cp.async.wait_group 0;" ::: "memory")

// ================= K_prep: transpose+split weights to bf16 hi/lo; zero accumulators =================
__global__ void k_prep(const float* __restrict__ sw1, const float* __restrict__ cw1) {
    int id = blockIdx.x * 256 + threadIdx.x;     // 32768
    int n = id >> 8, k = id & 255;               // n in [0,128), k in [0,256)
    float vs = sw1[(size_t)k * NHH + n];
    float vc = cw1[(size_t)k * NHH + n];
    __nv_bfloat16 hs = __float2bfloat16_rn(vs);
    __nv_bfloat16 ls = __float2bfloat16_rn(vs - __bfloat162float(hs));
    __nv_bfloat16 hc = __float2bfloat16_rn(vc);
    __nv_bfloat16 lc = __float2bfloat16_rn(vc - __bfloat162float(hc));
    g_Bh[n * 256 + k] = hs;
    g_Bl[n * 256 + k] = ls;
    g_Bh[(128 + n) * 256 + k] = hc;
    g_Bl[(128 + n) * 256 + k] = lc;
    if (id < NB * NQG * NP) { g_W[id] = 0.f; g_T[id] = 0.f; }
    if (id < NB * NQG) { g_Z[id] = 0.f; g_cnt[id] = 0.f; }
}

// ================= K_mlp: pipelined mma.sync bf16 split-GEMM + fused epilogue =================
#define MT 128
#define KC 64
#define NCHUNK (NH/KC)
#define KST 72
#define SM_AH 0
#define SM_AL (128*KST)
#define SM_B0 (2*128*KST)
#define BBUF  (2*256*KST)
#define BLOFF (256*KST)
#define MLP_SMEM ((SM_B0 + 2*BBUF) * 2)

__device__ __forceinline__ void mma_bf16(float d[4], uint32_t a0, uint32_t a1,
                                         uint32_t a2, uint32_t a3,
                                         uint32_t b0, uint32_t b1) {
    asm volatile(
        "mma.sync.aligned.m16n8k16.row.col.f32.bf16.bf16.f32 "
        "{%0,%1,%2,%3}, {%4,%5,%6,%7}, {%8,%9}, {%0,%1,%2,%3};"
        : "+f"(d[0]), "+f"(d[1]), "+f"(d[2]), "+f"(d[3])
        : "r"(a0), "r"(a1), "r"(a2), "r"(a3), "r"(b0), "r"(b1));
}

__global__ __launch_bounds__(512, 1)
void k_mlp(const float* __restrict__ x,
           const float* __restrict__ sb1, const float* __restrict__ sb2,
           const float* __restrict__ cb1, const float* __restrict__ cb2,
           const float* __restrict__ sw2, const float* __restrict__ cw2)
{
    extern __shared__ __nv_bfloat16 sm[];
    __shared__ float b1s[256], w2s[256];
    __shared__ float part[128][4];

    const int tid  = threadIdx.x;
    const int wid  = tid >> 5;
    const int lane = tid & 31;
    const int gid  = lane >> 2;
    const int tig  = lane & 3;
    const int mw   = wid & 3;
    const int nw   = wid >> 2;
    const int m0w  = mw * 32;
    const int n0w  = nw * 64;
    const int row0 = blockIdx.x * MT;
    const uint32_t smb = smem_u32(sm);

    if (tid < 256) {
        b1s[tid] = (tid < 128) ? sb1[tid] : cb1[tid - 128];
        w2s[tid] = (tid < 128) ? sw2[tid] : cw2[tid - 128];
    }

    float d[2][8][4];
    #pragma unroll
    for (int mi = 0; mi < 2; ++mi)
        #pragma unroll
        for (int ni = 0; ni < 8; ++ni)
            #pragma unroll
            for (int j = 0; j < 4; ++j) d[mi][ni][j] = 0.f;

    // ---- issue B chunk 0 (cp.async) ----
    #pragma unroll
    for (int i = 0; i < 4; ++i) {
        int idx = tid * 4 + i;
        int n = idx >> 3, k = (idx & 7) * 8;
        uint32_t dh = smb + 2 * (SM_B0 + n * KST + k);
        CP_ASYNC16(dh, &g_Bh[n * 256 + k]);
        CP_ASYNC16(dh + 2 * BLOFF, &g_Bl[n * 256 + k]);
    }
    CP_COMMIT();

    // ---- load A chunk 0 into regs ----
    float4 av[4];
    #pragma unroll
    for (int i = 0; i < 4; ++i) {
        int idx = tid * 4 + i;
        int row = idx >> 4, k = (idx & 15) * 4;
        av[i] = *(const float4*)&x[(size_t)(row0 + row) * NH + k];
    }

    for (int c = 0; c < NCHUNK; ++c) {
        const int buf = c & 1;
        if (c < NCHUNK - 1) {
            const int kb = (c + 1) * KC;
            #pragma unroll
            for (int i = 0; i < 4; ++i) {
                int idx = tid * 4 + i;
                int n = idx >> 3, k = (idx & 7) * 8;
                uint32_t dh = smb + 2 * (SM_B0 + (buf ^ 1) * BBUF + n * KST + k);
                CP_ASYNC16(dh, &g_Bh[n * 256 + kb + k]);
                CP_ASYNC16(dh + 2 * BLOFF, &g_Bl[n * 256 + kb + k]);
            }
            CP_COMMIT();
        }
        #pragma unroll
        for (int i = 0; i < 4; ++i) {
            int idx = tid * 4 + i;
            int row = idx >> 4, k = (idx & 15) * 4;
            float4 v = av[i];
            __nv_bfloat16 h0 = __float2bfloat16_rn(v.x), h1 = __float2bfloat16_rn(v.y);
            __nv_bfloat16 h2 = __float2bfloat16_rn(v.z), h3 = __float2bfloat16_rn(v.w);
            __nv_bfloat162 hA = {h0, h1}, hB = {h2, h3};
            __nv_bfloat162 lA = {__float2bfloat16_rn(v.x - __bfloat162float(h0)),
                                 __float2bfloat16_rn(v.y - __bfloat162float(h1))};
            __nv_bfloat162 lB = {__float2bfloat16_rn(v.z - __bfloat162float(h2)),
                                 __float2bfloat16_rn(v.w - __bfloat162float(h3))};
            uint2 hw = {*(uint32_t*)&hA, *(uint32_t*)&hB};
            uint2 lw = {*(uint32_t*)&lA, *(uint32_t*)&lB};
            *(uint2*)&sm[SM_AH + row * KST + k] = hw;
            *(uint2*)&sm[SM_AL + row * KST + k] = lw;
        }
        if (c < NCHUNK - 1) {
            const int kb = (c + 1) * KC;
            #pragma unroll
            for (int i = 0; i < 4; ++i) {
                int idx = tid * 4 + i;
                int row = idx >> 4, k = (idx & 15) * 4;
                av[i] = *(const float4*)&x[(size_t)(row0 + row) * NH + kb + k];
            }
        }
        if (c < NCHUNK - 1) { CP_WAIT1(); } else { CP_WAIT0(); }
        __syncthreads();

        const int B0 = SM_B0 + buf * BBUF;
        #pragma unroll
        for (int ks = 0; ks < KC / 16; ++ks) {
            const int kk = ks * 16;
            uint32_t ah[2][4], al[2][4];
            #pragma unroll
            for (int mi = 0; mi < 2; ++mi) {
                int off = (m0w + mi * 16 + gid) * KST + kk + 2 * tig;
                ah[mi][0] = *(const uint32_t*)&sm[SM_AH + off];
                ah[mi][1] = *(const uint32_t*)&sm[SM_AH + off + 8 * KST];
                ah[mi][2] = *(const uint32_t*)&sm[SM_AH + off + 8];
                ah[mi][3] = *(const uint32_t*)&sm[SM_AH + off + 8 * KST + 8];
                al[mi][0] = *(const uint32_t*)&sm[SM_AL + off];
                al[mi][1] = *(const uint32_t*)&sm[SM_AL + off + 8 * KST];
                al[mi][2] = *(const uint32_t*)&sm[SM_AL + off + 8];
                al[mi][3] = *(const uint32_t*)&sm[SM_AL + off + 8 * KST + 8];
            }
            #pragma unroll
            for (int ni = 0; ni < 8; ++ni) {
                int offb = B0 + (n0w + ni * 8 + gid) * KST + kk + 2 * tig;
                uint32_t b0 = *(const uint32_t*)&sm[offb];
                uint32_t b1 = *(const uint32_t*)&sm[offb + 8];
                #pragma unroll
                for (int mi = 0; mi < 2; ++mi) {
                    mma_bf16(d[mi][ni], ah[mi][0], ah[mi][1], ah[mi][2], ah[mi][3], b0, b1);
                    mma_bf16(d[mi][ni], al[mi][0], al[mi][1], al[mi][2], al[mi][3], b0, b1);
                }
            }
            #pragma unroll
            for (int ni = 0; ni < 8; ++ni) {
                int offb = B0 + BLOFF + (n0w + ni * 8 + gid) * KST + kk + 2 * tig;
                uint32_t b0 = *(const uint32_t*)&sm[offb];
                uint32_t b1 = *(const uint32_t*)&sm[offb + 8];
                #pragma unroll
                for (int mi = 0; mi < 2; ++mi)
                    mma_bf16(d[mi][ni], ah[mi][0], ah[mi][1], ah[mi][2], ah[mi][3], b0, b1);
            }
        }
        __syncthreads();
    }

    // ---- epilogue ----
    float p[2][2];
    #pragma unroll
    for (int mi = 0; mi < 2; ++mi) {
        p[mi][0] = 0.f; p[mi][1] = 0.f;
        #pragma unroll
        for (int ni = 0; ni < 8; ++ni) {
            int cb = n0w + ni * 8 + 2 * tig;
            #pragma unroll
            for (int j = 0; j < 2; ++j) {
                float h0 = fmaxf(d[mi][ni][j]     + b1s[cb + j], 0.f);
                float h1 = fmaxf(d[mi][ni][2 + j] + b1s[cb + j], 0.f);
                p[mi][0] = fmaf(h0, w2s[cb + j], p[mi][0]);
                p[mi][1] = fmaf(h1, w2s[cb + j], p[mi][1]);
            }
        }
    }
    #pragma unroll
    for (int off = 1; off <= 2; off <<= 1) {
        #pragma unroll
        for (int mi = 0; mi < 2; ++mi) {
            p[mi][0] += __shfl_xor_sync(0xffffffffu, p[mi][0], off);
            p[mi][1] += __shfl_xor_sync(0xffffffffu, p[mi][1], off);
        }
    }
    if (tig == 0) {
        #pragma unroll
        for (int mi = 0; mi < 2; ++mi) {
            part[m0w + mi * 16 + gid][nw]     = p[mi][0];
            part[m0w + mi * 16 + gid + 8][nw] = p[mi][1];
        }
    }
    __syncthreads();
    if (tid < 128) {
        int row = row0 + tid;
        float sv = part[tid][0] + part[tid][1] + sb2[0];
        float cl = part[tid][2] + part[tid][3] + cb2[0];
        g_e[row]    = __expf(fminf(sv, 80.f));      // no-max softmax term (NaN guard)
        g_conf[row] = 1.f / (1.f + __expf(-cl));
    }
}

// ================= K_accum: Z/count + per-group weighted sums =================
__global__ __launch_bounds__(256) void k_accum(const float* __restrict__ px,
                                               const int* __restrict__ qs) {
    const int b = blockIdx.x >> 5;
    const int chunk = blockIdx.x & 31;
    const int t0 = b * NS + chunk * 64;
    const int p = threadIdx.x & 63;
    const int u = threadIdx.x >> 6;
    const int bg = b * NQG;
    __shared__ float accW[4][NQG][NP];
    __shared__ float accT[4][NQG][NP];
    __shared__ float esh[64];
    __shared__ int   qsh[64];
    __shared__ float Zsh[NQG];
    __shared__ int   csh[NQG];
    if (threadIdx.x < NQG) { Zsh[threadIdx.x] = 0.f; csh[threadIdx.x] = 0; }
    #pragma unroll
    for (int g = 0; g < NQG; ++g) { accW[u][g][p] = 0.f; accT[u][g][p] = 0.f; }
    __syncthreads();
    if (threadIdx.x < 64) {
        int q = qs[t0 + threadIdx.x];
        qsh[threadIdx.x] = q;
        float e = g_e[t0 + threadIdx.x];
        esh[threadIdx.x] = e;
        atomicAdd(&Zsh[q], e);
        atomicAdd(&csh[q], 1);
    }
    __syncthreads();
    const int tb = u * 16;
    float pxv[16];
    const float* base = px + (size_t)(t0 + tb) * NP + p;
    #pragma unroll
    for (int k = 0; k < 16; ++k) pxv[k] = base[(size_t)k * NP];
    #pragma unroll
    for (int k = 0; k < 16; ++k) {
        int g = qsh[tb + k];
        accW[u][g][p] = fmaf(esh[tb + k], pxv[k], accW[u][g][p]);
        accT[u][g][p] += pxv[k];
    }
    __syncthreads();
    for (int i = threadIdx.x; i < NQG * NP; i += 256) {
        int g = i >> 6, pp = i & 63;
        float w = accW[0][g][pp] + accW[1][g][pp] + accW[2][g][pp] + accW[3][g][pp];
        float t = accT[0][g][pp] + accT[1][g][pp] + accT[2][g][pp] + accT[3][g][pp];
        atomicAdd(&g_W[bg * NP + i], w);
        atomicAdd(&g_T[bg * NP + i], t);
    }
    if (threadIdx.x < NQG) {
        atomicAdd(&g_Z[bg + threadIdx.x], Zsh[threadIdx.x]);
        atomicAdd(&g_cnt[bg + threadIdx.x], (float)csh[threadIdx.x]);
    }
}

// ================= K_out: V finalize (per block, cheap) + streaming blend =================
__global__ __launch_bounds__(256) void k_out(const float* __restrict__ px,
                                             const int* __restrict__ qs,
                                             float* __restrict__ out) {
    const int b = blockIdx.x >> 4;
    const int chunk = blockIdx.x & 15;
    const int t0 = b * NS + chunk * 128;
    const int bg = b * NQG;
    const int tid = threadIdx.x;
    const int p  = tid & 63;
    const int c4 = tid >> 6;
    __shared__ float Tl[NQG][NP];
    __shared__ float V[NQG][NP];
    __shared__ float tpart[4][NP];
    __shared__ float invZ[NQG];
    __shared__ float csm[128];
    __shared__ int   qsm[128];
    // phase 1: load T (L2-hot), Z/cnt, conf/qs
    for (int i = tid; i < NQG * NP; i += 256)
        Tl[i >> 6][i & 63] = g_T[bg * NP + i];
    if (tid < NQG)
        invZ[tid] = 1.f / (g_Z[bg + tid] + ((float)NS - g_cnt[bg + tid]));
    if (tid >= 64 && tid < 192) {
        int t = tid - 64;
        csm[t] = g_conf[t0 + t];
        qsm[t] = qs[t0 + t];
    }
    __syncthreads();
    // phase 2: tall[p] = sum_g T[g][p] (parallel partials)
    {
        float t = 0.f;
        #pragma unroll
        for (int g = 0; g < NQG; g += 4) t += Tl[g + c4][p];
        tpart[c4][p] = t;
    }
    __syncthreads();
    // phase 3: V
    for (int i = tid; i < NQG * NP; i += 256) {
        int g = i >> 6, pp = i & 63;
        float tall = tpart[0][pp] + tpart[1][pp] + tpart[2][pp] + tpart[3][pp];
        V[g][pp] = (g_W[bg * NP + i] + tall - Tl[g][pp]) * invZ[g];
    }
    __syncthreads();
    // phase 4: stream 128 tokens (2048 float4)
    #pragma unroll
    for (int it = 0; it < 8; ++it) {
        int i  = it * 256 + tid;
        int t  = i >> 4, pq = i & 15;
        int tok = t0 + t;
        float c = csm[t];
        int q = qsm[t];
        float4 pv = *(const float4*)&px[(size_t)tok * NP + pq * 4];
        float4 vv = *(const float4*)&V[q][pq * 4];
        float ic = 1.f - c;
        float4 o;
        o.x = fmaf(c, pv.x, ic * vv.x);
        o.y = fmaf(c, pv.y, ic * vv.y);
        o.z = fmaf(c, pv.z, ic * vv.z);
        o.w = fmaf(c, pv.w, ic * vv.w);
        *(float4*)&out[(size_t)tok * NP + pq * 4] = o;
    }
}

extern "C" void kernel_launch(void* const* d_in, const int* in_sizes, int n_in,
                              void* d_out, int out_size) {
    const float* x   = (const float*)d_in[0];
    const float* px  = (const float*)d_in[1];
    const float* sw1 = (const float*)d_in[2];
    const float* sb1 = (const float*)d_in[3];
    const float* sw2 = (const float*)d_in[4];
    const float* sb2 = (const float*)d_in[5];
    const float* cw1 = (const float*)d_in[6];
    const float* cb1 = (const float*)d_in[7];
    const float* cw2 = (const float*)d_in[8];
    const float* cb2 = (const float*)d_in[9];
    const int*   qs  = (const int*)d_in[10];
    float* out = (float*)d_out;

    cudaFuncSetAttribute(k_mlp, cudaFuncAttributeMaxDynamicSharedMemorySize, MLP_SMEM);

    k_prep<<<128, 256>>>(sw1, cw1);
    k_mlp<<<NTOK / MT, 512, MLP_SMEM>>>(x, sb1, sb2, cb1, cb2, sw2, cw2);
    k_accum<<<NB * 32, 256>>>(px, qs);
    k_out<<<NB * 16, 256>>>(px, qs, out);
}

// round 9
// speedup vs baseline: 1.1042x; 1.0394x over previous
#include <cuda_runtime.h>
#include <cuda_bf16.h>
#include <cstdint>

#define NB   8
#define NS   2048
#define NH   256
#define NHH  128
#define NP   64
#define NQG  20
#define NTOK (NB*NS)

// ---- scratch (device globals; no allocation allowed) ----
__device__ float g_e[NTOK];              // exp(sim logit), clamped
__device__ float g_conf[NTOK];           // sigmoid(conf logit)
__device__ float g_Z[NB*NQG];            // in-group sum of exp
__device__ float g_cnt[NB*NQG];          // group counts
__device__ float g_W[NB*NQG*NP];         // exp-weighted param sums
__device__ float g_T[NB*NQG*NP];         // plain param sums
__device__ __nv_bfloat16 g_Bh[256*256];  // weights [n=256][k=256], bf16 hi
__device__ __nv_bfloat16 g_Bl[256*256];  // bf16 lo residual

__device__ __forceinline__ uint32_t smem_u32(const void* p) {
    uint32_t a;
    asm("{ .reg .u64 t; cvta.to.shared.u64 t, %1; cvt.u32.u64 %0, t; }" : "=r"(a) : "l"(p));
    return a;
}
#define CP_ASYNC16(smaddr, gptr) \
    asm volatile("cp.async.cg.shared.global [%0], [%1], 16;" :: "r"(smaddr), "l"(gptr))
#define CP_COMMIT() asm volatile("cp.async.commit_group;" ::: "memory")
#define CP_WAIT1()  asm volatile("cp.async.wait_group 1;" ::: "memory")
#define CP_WAIT0()  asm volatile("cp.async.wait_group 0;" ::: "memory")

// ================= K_prep: transpose+split weights to bf16 hi/lo; zero accumulators =================
__global__ void k_prep(const float* __restrict__ sw1, const float* __restrict__ cw1) {
    int id = blockIdx.x * 256 + threadIdx.x;     // 32768
    int n = id >> 8, k = id & 255;               // n in [0,128), k in [0,256)
    float vs = sw1[(size_t)k * NHH + n];
    float vc = cw1[(size_t)k * NHH + n];
    __nv_bfloat16 hs = __float2bfloat16_rn(vs);
    __nv_bfloat16 ls = __float2bfloat16_rn(vs - __bfloat162float(hs));
    __nv_bfloat16 hc = __float2bfloat16_rn(vc);
    __nv_bfloat16 lc = __float2bfloat16_rn(vc - __bfloat162float(hc));
    g_Bh[n * 256 + k] = hs;
    g_Bl[n * 256 + k] = ls;
    g_Bh[(128 + n) * 256 + k] = hc;
    g_Bl[(128 + n) * 256 + k] = lc;
    if (id < NB * NQG * NP) { g_W[id] = 0.f; g_T[id] = 0.f; }
    if (id < NB * NQG) { g_Z[id] = 0.f; g_cnt[id] = 0.f; }
}

// ================= K_mlp: pipelined mma.sync bf16 split-GEMM + fused epilogue =================
#define MT 128
#define KC 64
#define NCHUNK (NH/KC)
#define KST 72
#define SM_AH 0
#define SM_AL (128*KST)
#define SM_B0 (2*128*KST)
#define BBUF  (2*256*KST)
#define BLOFF (256*KST)
#define MLP_SMEM ((SM_B0 + 2*BBUF) * 2)

__device__ __forceinline__ void mma_bf16(float d[4], uint32_t a0, uint32_t a1,
                                         uint32_t a2, uint32_t a3,
                                         uint32_t b0, uint32_t b1) {
    asm volatile(
        "mma.sync.aligned.m16n8k16.row.col.f32.bf16.bf16.f32 "
        "{%0,%1,%2,%3}, {%4,%5,%6,%7}, {%8,%9}, {%0,%1,%2,%3};"
        : "+f"(d[0]), "+f"(d[1]), "+f"(d[2]), "+f"(d[3])
        : "r"(a0), "r"(a1), "r"(a2), "r"(a3), "r"(b0), "r"(b1));
}

__global__ __launch_bounds__(512, 1)
void k_mlp(const float* __restrict__ x,
           const float* __restrict__ sb1, const float* __restrict__ sb2,
           const float* __restrict__ cb1, const float* __restrict__ cb2,
           const float* __restrict__ sw2, const float* __restrict__ cw2)
{
    extern __shared__ __nv_bfloat16 sm[];
    __shared__ float b1s[256], w2s[256];
    __shared__ float part[128][4];

    const int tid  = threadIdx.x;
    const int wid  = tid >> 5;
    const int lane = tid & 31;
    const int gid  = lane >> 2;
    const int tig  = lane & 3;
    const int mw   = wid & 3;
    const int nw   = wid >> 2;
    const int m0w  = mw * 32;
    const int n0w  = nw * 64;
    const int row0 = blockIdx.x * MT;
    const uint32_t smb = smem_u32(sm);

    if (tid < 256) {
        b1s[tid] = (tid < 128) ? sb1[tid] : cb1[tid - 128];
        w2s[tid] = (tid < 128) ? sw2[tid] : cw2[tid - 128];
    }

    float d[2][8][4];
    #pragma unroll
    for (int mi = 0; mi < 2; ++mi)
        #pragma unroll
        for (int ni = 0; ni < 8; ++ni)
            #pragma unroll
            for (int j = 0; j < 4; ++j) d[mi][ni][j] = 0.f;

    // ---- issue B chunk 0 (cp.async) ----
    #pragma unroll
    for (int i = 0; i < 4; ++i) {
        int idx = tid * 4 + i;
        int n = idx >> 3, k = (idx & 7) * 8;
        uint32_t dh = smb + 2 * (SM_B0 + n * KST + k);
        CP_ASYNC16(dh, &g_Bh[n * 256 + k]);
        CP_ASYNC16(dh + 2 * BLOFF, &g_Bl[n * 256 + k]);
    }
    CP_COMMIT();

    // ---- load A chunk 0 into regs ----
    float4 av[4];
    #pragma unroll
    for (int i = 0; i < 4; ++i) {
        int idx = tid * 4 + i;
        int row = idx >> 4, k = (idx & 15) * 4;
        av[i] = *(const float4*)&x[(size_t)(row0 + row) * NH + k];
    }

    for (int c = 0; c < NCHUNK; ++c) {
        const int buf = c & 1;
        if (c < NCHUNK - 1) {
            const int kb = (c + 1) * KC;
            #pragma unroll
            for (int i = 0; i < 4; ++i) {
                int idx = tid * 4 + i;
                int n = idx >> 3, k = (idx & 7) * 8;
                uint32_t dh = smb + 2 * (SM_B0 + (buf ^ 1) * BBUF + n * KST + k);
                CP_ASYNC16(dh, &g_Bh[n * 256 + kb + k]);
                CP_ASYNC16(dh + 2 * BLOFF, &g_Bl[n * 256 + kb + k]);
            }
            CP_COMMIT();
        }
        #pragma unroll
        for (int i = 0; i < 4; ++i) {
            int idx = tid * 4 + i;
            int row = idx >> 4, k = (idx & 15) * 4;
            float4 v = av[i];
            __nv_bfloat16 h0 = __float2bfloat16_rn(v.x), h1 = __float2bfloat16_rn(v.y);
            __nv_bfloat16 h2 = __float2bfloat16_rn(v.z), h3 = __float2bfloat16_rn(v.w);
            __nv_bfloat162 hA = {h0, h1}, hB = {h2, h3};
            __nv_bfloat162 lA = {__float2bfloat16_rn(v.x - __bfloat162float(h0)),
                                 __float2bfloat16_rn(v.y - __bfloat162float(h1))};
            __nv_bfloat162 lB = {__float2bfloat16_rn(v.z - __bfloat162float(h2)),
                                 __float2bfloat16_rn(v.w - __bfloat162float(h3))};
            uint2 hw = {*(uint32_t*)&hA, *(uint32_t*)&hB};
            uint2 lw = {*(uint32_t*)&lA, *(uint32_t*)&lB};
            *(uint2*)&sm[SM_AH + row * KST + k] = hw;
            *(uint2*)&sm[SM_AL + row * KST + k] = lw;
        }
        if (c < NCHUNK - 1) {
            const int kb = (c + 1) * KC;
            #pragma unroll
            for (int i = 0; i < 4; ++i) {
                int idx = tid * 4 + i;
                int row = idx >> 4, k = (idx & 15) * 4;
                av[i] = *(const float4*)&x[(size_t)(row0 + row) * NH + kb + k];
            }
        }
        if (c < NCHUNK - 1) { CP_WAIT1(); } else { CP_WAIT0(); }
        __syncthreads();

        const int B0 = SM_B0 + buf * BBUF;
        #pragma unroll
        for (int ks = 0; ks < KC / 16; ++ks) {
            const int kk = ks * 16;
            uint32_t ah[2][4], al[2][4];
            #pragma unroll
            for (int mi = 0; mi < 2; ++mi) {
                int off = (m0w + mi * 16 + gid) * KST + kk + 2 * tig;
                ah[mi][0] = *(const uint32_t*)&sm[SM_AH + off];
                ah[mi][1] = *(const uint32_t*)&sm[SM_AH + off + 8 * KST];
                ah[mi][2] = *(const uint32_t*)&sm[SM_AH + off + 8];
                ah[mi][3] = *(const uint32_t*)&sm[SM_AH + off + 8 * KST + 8];
                al[mi][0] = *(const uint32_t*)&sm[SM_AL + off];
                al[mi][1] = *(const uint32_t*)&sm[SM_AL + off + 8 * KST];
                al[mi][2] = *(const uint32_t*)&sm[SM_AL + off + 8];
                al[mi][3] = *(const uint32_t*)&sm[SM_AL + off + 8 * KST + 8];
            }
            #pragma unroll
            for (int ni = 0; ni < 8; ++ni) {
                int offb = B0 + (n0w + ni * 8 + gid) * KST + kk + 2 * tig;
                uint32_t b0 = *(const uint32_t*)&sm[offb];
                uint32_t b1 = *(const uint32_t*)&sm[offb + 8];
                #pragma unroll
                for (int mi = 0; mi < 2; ++mi) {
                    mma_bf16(d[mi][ni], ah[mi][0], ah[mi][1], ah[mi][2], ah[mi][3], b0, b1);
                    mma_bf16(d[mi][ni], al[mi][0], al[mi][1], al[mi][2], al[mi][3], b0, b1);
                }
            }
            #pragma unroll
            for (int ni = 0; ni < 8; ++ni) {
                int offb = B0 + BLOFF + (n0w + ni * 8 + gid) * KST + kk + 2 * tig;
                uint32_t b0 = *(const uint32_t*)&sm[offb];
                uint32_t b1 = *(const uint32_t*)&sm[offb + 8];
                #pragma unroll
                for (int mi = 0; mi < 2; ++mi)
                    mma_bf16(d[mi][ni], ah[mi][0], ah[mi][1], ah[mi][2], ah[mi][3], b0, b1);
            }
        }
        __syncthreads();
    }

    // ---- epilogue ----
    float p[2][2];
    #pragma unroll
    for (int mi = 0; mi < 2; ++mi) {
        p[mi][0] = 0.f; p[mi][1] = 0.f;
        #pragma unroll
        for (int ni = 0; ni < 8; ++ni) {
            int cb = n0w + ni * 8 + 2 * tig;
            #pragma unroll
            for (int j = 0; j < 2; ++j) {
                float h0 = fmaxf(d[mi][ni][j]     + b1s[cb + j], 0.f);
                float h1 = fmaxf(d[mi][ni][2 + j] + b1s[cb + j], 0.f);
                p[mi][0] = fmaf(h0, w2s[cb + j], p[mi][0]);
                p[mi][1] = fmaf(h1, w2s[cb + j], p[mi][1]);
            }
        }
    }
    #pragma unroll
    for (int off = 1; off <= 2; off <<= 1) {
        #pragma unroll
        for (int mi = 0; mi < 2; ++mi) {
            p[mi][0] += __shfl_xor_sync(0xffffffffu, p[mi][0], off);
            p[mi][1] += __shfl_xor_sync(0xffffffffu, p[mi][1], off);
        }
    }
    if (tig == 0) {
        #pragma unroll
        for (int mi = 0; mi < 2; ++mi) {
            part[m0w + mi * 16 + gid][nw]     = p[mi][0];
            part[m0w + mi * 16 + gid + 8][nw] = p[mi][1];
        }
    }
    __syncthreads();
    if (tid < 128) {
        int row = row0 + tid;
        float sv = part[tid][0] + part[tid][1] + sb2[0];
        float cl = part[tid][2] + part[tid][3] + cb2[0];
        g_e[row]    = __expf(fminf(sv, 80.f));      // no-max softmax term (NaN guard)
        g_conf[row] = 1.f / (1.f + __expf(-cl));
    }
}

// ================= K_accum: Z/count + per-group weighted sums =================
__global__ __launch_bounds__(256) void k_accum(const float* __restrict__ px,
                                               const int* __restrict__ qs) {
    const int b = blockIdx.x >> 5;
    const int chunk = blockIdx.x & 31;
    const int t0 = b * NS + chunk * 64;
    const int p = threadIdx.x & 63;
    const int u = threadIdx.x >> 6;
    const int bg = b * NQG;
    __shared__ float accW[4][NQG][NP];
    __shared__ float accT[4][NQG][NP];
    __shared__ float esh[64];
    __shared__ int   qsh[64];
    __shared__ float Zsh[NQG];
    __shared__ int   csh[NQG];
    if (threadIdx.x < NQG) { Zsh[threadIdx.x] = 0.f; csh[threadIdx.x] = 0; }
    #pragma unroll
    for (int g = 0; g < NQG; ++g) { accW[u][g][p] = 0.f; accT[u][g][p] = 0.f; }
    __syncthreads();
    if (threadIdx.x < 64) {
        int q = qs[t0 + threadIdx.x];
        qsh[threadIdx.x] = q;
        float e = g_e[t0 + threadIdx.x];
        esh[threadIdx.x] = e;
        atomicAdd(&Zsh[q], e);
        atomicAdd(&csh[q], 1);
    }
    __syncthreads();
    const int tb = u * 16;
    float pxv[16];
    const float* base = px + (size_t)(t0 + tb) * NP + p;
    #pragma unroll
    for (int k = 0; k < 16; ++k) pxv[k] = base[(size_t)k * NP];
    #pragma unroll
    for (int k = 0; k < 16; ++k) {
        int g = qsh[tb + k];
        accW[u][g][p] = fmaf(esh[tb + k], pxv[k], accW[u][g][p]);
        accT[u][g][p] += pxv[k];
    }
    __syncthreads();
    for (int i = threadIdx.x; i < NQG * NP; i += 256) {
        int g = i >> 6, pp = i & 63;
        float w = accW[0][g][pp] + accW[1][g][pp] + accW[2][g][pp] + accW[3][g][pp];
        float t = accT[0][g][pp] + accT[1][g][pp] + accT[2][g][pp] + accT[3][g][pp];
        atomicAdd(&g_W[bg * NP + i], w);
        atomicAdd(&g_T[bg * NP + i], t);
    }
    if (threadIdx.x < NQG) {
        atomicAdd(&g_Z[bg + threadIdx.x], Zsh[threadIdx.x]);
        atomicAdd(&g_cnt[bg + threadIdx.x], (float)csh[threadIdx.x]);
    }
}

// ================= K_out: V finalize (per block) + streaming blend, 32 tok/block =================
__global__ __launch_bounds__(256) void k_out(const float* __restrict__ px,
                                             const int* __restrict__ qs,
                                             float* __restrict__ out) {
    const int b = blockIdx.x >> 6;
    const int chunk = blockIdx.x & 63;
    const int t0 = b * NS + chunk * 32;
    const int bg = b * NQG;
    const int tid = threadIdx.x;
    const int p  = tid & 63;
    const int c4 = tid >> 6;
    __shared__ float Tl[NQG][NP];
    __shared__ float V[NQG][NP];
    __shared__ float tpart[4][NP];
    __shared__ float invZ[NQG];
    __shared__ float csm[32];
    __shared__ int   qsm[32];
    // phase 1: load T (L2-hot), Z/cnt, conf/qs
    for (int i = tid; i < NQG * NP; i += 256)
        Tl[i >> 6][i & 63] = g_T[bg * NP + i];
    if (tid < NQG)
        invZ[tid] = 1.f / (g_Z[bg + tid] + ((float)NS - g_cnt[bg + tid]));
    if (tid >= 64 && tid < 96) {
        int t = tid - 64;
        csm[t] = g_conf[t0 + t];
        qsm[t] = qs[t0 + t];
    }
    __syncthreads();
    // phase 2: tall[p] = sum_g T[g][p] (parallel partials)
    {
        float t = 0.f;
        #pragma unroll
        for (int g = 0; g < NQG; g += 4) t += Tl[g + c4][p];
        tpart[c4][p] = t;
    }
    __syncthreads();
    // phase 3: V
    for (int i = tid; i < NQG * NP; i += 256) {
        int g = i >> 6, pp = i & 63;
        float tall = tpart[0][pp] + tpart[1][pp] + tpart[2][pp] + tpart[3][pp];
        V[g][pp] = (g_W[bg * NP + i] + tall - Tl[g][pp]) * invZ[g];
    }
    __syncthreads();
    // phase 4: stream 32 tokens (512 float4)
    #pragma unroll
    for (int it = 0; it < 2; ++it) {
        int i  = it * 256 + tid;
        int t  = i >> 4, pq = i & 15;
        int tok = t0 + t;
        float c = csm[t];
        int q = qsm[t];
        float4 pv = *(const float4*)&px[(size_t)tok * NP + pq * 4];
        float4 vv = *(const float4*)&V[q][pq * 4];
        float ic = 1.f - c;
        float4 o;
        o.x = fmaf(c, pv.x, ic * vv.x);
        o.y = fmaf(c, pv.y, ic * vv.y);
        o.z = fmaf(c, pv.z, ic * vv.z);
        o.w = fmaf(c, pv.w, ic * vv.w);
        *(float4*)&out[(size_t)tok * NP + pq * 4] = o;
    }
}

extern "C" void kernel_launch(void* const* d_in, const int* in_sizes, int n_in,
                              void* d_out, int out_size) {
    const float* x   = (const float*)d_in[0];
    const float* px  = (const float*)d_in[1];
    const float* sw1 = (const float*)d_in[2];
    const float* sb1 = (const float*)d_in[3];
    const float* sw2 = (const float*)d_in[4];
    const float* sb2 = (const float*)d_in[5];
    const float* cw1 = (const float*)d_in[6];
    const float* cb1 = (const float*)d_in[7];
    const float* cw2 = (const float*)d_in[8];
    const float* cb2 = (const float*)d_in[9];
    const int*   qs  = (const int*)d_in[10];
    float* out = (float*)d_out;

    cudaFuncSetAttribute(k_mlp, cudaFuncAttributeMaxDynamicSharedMemorySize, MLP_SMEM);

    k_prep<<<128, 256>>>(sw1, cw1);
    k_mlp<<<NTOK / MT, 512, MLP_SMEM>>>(x, sb1, sb2, cb1, cb2, sw2, cw2);
    k_accum<<<NB * 32, 256>>>(px, qs);
    k_out<<<NB * 64, 256>>>(px, qs, out);
}